// round 4
// baseline (speedup 1.0000x reference)
#include <cuda_runtime.h>
#include <cuda_bf16.h>
#include <cstddef>

#define BATCH    256
#define DATA_DIM 8192
#define NNZ      256
#define QK       64
#define EMB      63
#define NSUB     8
#define K0S      260   // stride (floats) for transposed k0 staging; 260 mod 32 = 4 -> conflict-free LDS.128

// Precomputed per-row projections of the embedding table (row 0 = padding row).
__device__ float4 g_Q0T[(DATA_DIM + 1) * 16];
__device__ float4 g_K0T[(DATA_DIM + 1) * 16];

// packed f32x2 ops
__device__ __forceinline__ void fma2(unsigned long long& acc,
                                     unsigned long long a,
                                     unsigned long long b) {
    asm("fma.rn.f32x2 %0, %1, %2, %0;" : "+l"(acc) : "l"(a), "l"(b));
}
__device__ __forceinline__ unsigned long long fma2n(unsigned long long a,
                                                    unsigned long long b,
                                                    unsigned long long c) {
    unsigned long long d;
    asm("fma.rn.f32x2 %0, %1, %2, %3;" : "=l"(d) : "l"(a), "l"(b), "l"(c));
    return d;
}
__device__ __forceinline__ float hsum2(unsigned long long a) {
    return __uint_as_float((unsigned)a) + __uint_as_float((unsigned)(a >> 32));
}

// ---------------------------------------------------------------------------
// Kernel P (round-1 version: stride-65 shared transpose, conflict-free).
// Q0T[p][d] = bq[d] + sum_e embed[p][e] * Wq[d][e+1]   (same for K)
// ---------------------------------------------------------------------------
__global__ void __launch_bounds__(256)
precompute_kernel(const float* __restrict__ embed,
                  const float* __restrict__ Wq,
                  const float* __restrict__ bq,
                  const float* __restrict__ Wk,
                  const float* __restrict__ bk) {
    __shared__ float WqT[64 * 65];
    __shared__ float WkT[64 * 65];
    __shared__ float bqs[64], bks[64];
    __shared__ float es[4][64];

    const int tid = threadIdx.x;
    for (int i = tid; i < 4096; i += 256) {
        int d = i >> 6, j = i & 63;
        WqT[j * 65 + d] = Wq[i];   // (j + d) mod 32 distinct within warp -> conflict-free
        WkT[j * 65 + d] = Wk[i];
    }
    if (tid < 64) { bqs[tid] = bq[tid]; bks[tid] = bk[tid]; }
    __syncthreads();

    const int d = tid & 63, r = tid >> 6;
    for (int it = 0; it < 16; ++it) {
        int p = blockIdx.x * 64 + it * 4 + r;
        if (d < EMB && p <= DATA_DIM) es[r][d] = embed[(size_t)p * EMB + d];
        __syncthreads();
        if (p <= DATA_DIM) {
            float q = bqs[d], k = bks[d];
#pragma unroll
            for (int e = 0; e < EMB; ++e) {
                float ev = es[r][e];
                q += ev * WqT[(e + 1) * 65 + d];
                k += ev * WkT[(e + 1) * 65 + d];
            }
            reinterpret_cast<float*>(g_Q0T)[(size_t)p * QK + d] = q;
            reinterpret_cast<float*>(g_K0T)[(size_t)p * QK + d] = k;
        }
        __syncthreads();
    }
}

// ---------------------------------------------------------------------------
// Kernel C: per-batch condense + RK4 integration + scatter of both planes.
// k0 columns + q0 row live in REGISTERS; per eval only w and s cross shared
// memory (broadcast LDS.128). w^2 folded into the m-loop; a folded into the
// q-loop; a single shfl tree remains (for g = sum_i w_i f_i).
// ---------------------------------------------------------------------------
struct SmemC {
    __align__(16) float k0[64 * K0S];   // transient transpose staging only
    __align__(16) float wsh[NNZ];
    __align__(16) float s[QK];
    __align__(16) float av[QK];         // a = Wq[:,0]
    __align__(16) float mpart[256];     // K0^T w chunk partials
    __align__(16) float m2part[256];    // w^2 chunk partials
    __align__(16) float red2[8];        // per-warp w*f partials
    __align__(16) float val[NNZ];
    int   idx[NNZ];
    int   wscan[8];
};

extern __shared__ unsigned char smem_raw[];

__global__ void __launch_bounds__(256, 2)
integrate_kernel(const float* __restrict__ t,
                 const float* __restrict__ x,
                 const float* __restrict__ Wq,
                 const float* __restrict__ Wk,
                 float* __restrict__ out) {
    SmemC* sm = reinterpret_cast<SmemC*>(smem_raw);
    const int tid  = threadIdx.x;
    const int b    = blockIdx.x;
    const int lane = tid & 31;
    const int wid  = tid >> 5;

    // ---- Phase 0: zero this block's two output rows ----
    {
        float4 z = make_float4(0.f, 0.f, 0.f, 0.f);
        float4* o4 = reinterpret_cast<float4*>(out);
        for (int i = tid; i < 2048; i += 256) {
            o4[(size_t)b * 2048 + i] = z;
            o4[(size_t)(BATCH + b) * 2048 + i] = z;
        }
    }

    // ---- Phase 1: scan + order-preserving compaction ----
    float xr[32];
    {
        const float4* xrow4 = reinterpret_cast<const float4*>(x + (size_t)b * DATA_DIM) + tid * 8;
#pragma unroll
        for (int j = 0; j < 8; ++j) {
            float4 f = xrow4[j];
            xr[4 * j + 0] = f.x; xr[4 * j + 1] = f.y;
            xr[4 * j + 2] = f.z; xr[4 * j + 3] = f.w;
        }
    }
    if (tid < NNZ) { sm->val[tid] = 0.0f; sm->idx[tid] = 0; }
    if (tid < QK)  { sm->av[tid] = Wq[tid * 64]; }

    int cnt = 0;
#pragma unroll
    for (int j = 0; j < 32; ++j) cnt += (xr[j] != 0.0f) ? 1 : 0;
    int inc = cnt;
#pragma unroll
    for (int o = 1; o < 32; o <<= 1) {
        int u = __shfl_up_sync(0xffffffffu, inc, o);
        if (lane >= o) inc += u;
    }
    if (lane == 31) sm->wscan[wid] = inc;
    __syncthreads();
    int woff = 0;
#pragma unroll
    for (int wdx = 0; wdx < 8; ++wdx) woff += (wdx < wid) ? sm->wscan[wdx] : 0;
    int o = woff + inc - cnt;  // exclusive prefix
#pragma unroll
    for (int j = 0; j < 32; ++j) {
        float v = xr[j];
        if (v != 0.0f && o < NNZ) {
            sm->val[o] = v;
            sm->idx[o] = tid * 32 + j;
            ++o;
        }
    }
    __syncthreads();

    // ---- Phase 2: q0 row -> regs; k0 transpose-stage -> column regs ----
    const int p     = sm->idx[tid] + 1;
    const float myv = sm->val[tid];

    out[(size_t)b * DATA_DIM + (p - 1)] = myv;   // t=0 plane

    ulonglong2 q0p[16];   // my row of Q0 (64 floats, packed pairs)
    {
        const ulonglong2* qrow = reinterpret_cast<const ulonglong2*>(g_Q0T + (size_t)p * 16);
#pragma unroll
        for (int i = 0; i < 16; ++i) q0p[i] = qrow[i];
        const float4* krow = g_K0T + (size_t)p * 16;
#pragma unroll
        for (int i = 0; i < 16; ++i) {
            float4 f = krow[i];
            int d = 4 * i;
            sm->k0[(d + 0) * K0S + tid] = f.x;
            sm->k0[(d + 1) * K0S + tid] = f.y;
            sm->k0[(d + 2) * K0S + tid] = f.z;
            sm->k0[(d + 3) * K0S + tid] = f.w;
        }
    }

    float bvd = 0.0f;
    if (tid < QK) bvd = Wk[tid * 64];   // b = Wk[:,0]

    const float dt = (t[1] - t[0]) * (1.0f / (float)NSUB);
    const int dd = tid & 63, cc = tid >> 6;
    __syncthreads();

    // my k0 column chunk: K0[dd][64*cc .. 64*cc+63] into 32 packed regs
    ulonglong2 k0p[16];
    {
        const ulonglong2* krowsh =
            reinterpret_cast<const ulonglong2*>(sm->k0 + dd * K0S + cc * 64);
#pragma unroll
        for (int j = 0; j < 16; ++j) k0p[j] = krowsh[j];
    }

    const ulonglong2* wvp = reinterpret_cast<const ulonglong2*>(sm->wsh + cc * 64);
    const ulonglong2* svp = reinterpret_cast<const ulonglong2*>(sm->s);
    const ulonglong2* avp = reinterpret_cast<const ulonglong2*>(sm->av);

    // dxdt(w) = w*(f - g);  s = S2*b + K0^T w;
    // f_i = ( sum_d (a_d*w_i + q0_id) * s_d ) / 8;  g = sum_j w_j f_j
    // precondition: sm->wsh staged + synced
    auto dxdt = [&](float w) -> float {
        // m + w^2 partials over chunk cc (register FMAs, broadcast w reads)
        unsigned long long a0 = 0ull, a1 = 0ull, b0 = 0ull, b1 = 0ull;
#pragma unroll
        for (int j = 0; j < 16; ++j) {
            ulonglong2 wv = wvp[j];
            fma2(a0, k0p[j].x, wv.x);
            fma2(a1, k0p[j].y, wv.y);
            fma2(b0, wv.x, wv.x);
            fma2(b1, wv.y, wv.y);
        }
        sm->mpart[tid]  = hsum2(a0) + hsum2(a1);
        sm->m2part[tid] = hsum2(b0) + hsum2(b1);
        __syncthreads();

        if (tid < QK) {
            float m  = sm->mpart[tid]  + sm->mpart[tid + 64]  +
                       sm->mpart[tid + 128]  + sm->mpart[tid + 192];
            float S2 = sm->m2part[tid] + sm->m2part[tid + 64] +
                       sm->m2part[tid + 128] + sm->m2part[tid + 192];
            sm->s[tid] = S2 * bvd + m;
        }
        __syncthreads();

        // f via a-fold: acc += (a*w + q0) * s
        unsigned u = __float_as_uint(w);
        unsigned long long wpk = ((unsigned long long)u << 32) | u;
        unsigned long long q0 = 0ull, q1 = 0ull;
#pragma unroll
        for (int j = 0; j < 16; ++j) {
            ulonglong2 sv = svp[j];
            ulonglong2 av = avp[j];
            fma2(q0, fma2n(av.x, wpk, q0p[j].x), sv.x);
            fma2(q1, fma2n(av.y, wpk, q0p[j].y), sv.y);
        }
        float f = (hsum2(q0) + hsum2(q1)) * 0.125f;   // 1/sqrt(64)

        // g = sum_i w_i f_i (single remaining tree)
        float wf = w * f;
#pragma unroll
        for (int o2 = 16; o2 > 0; o2 >>= 1) wf += __shfl_xor_sync(0xffffffffu, wf, o2);
        if (lane == 0) sm->red2[wid] = wf;
        __syncthreads();
        float4 r2a = *reinterpret_cast<const float4*>(&sm->red2[0]);
        float4 r2b = *reinterpret_cast<const float4*>(&sm->red2[4]);
        float g = (r2a.x + r2a.y) + (r2a.z + r2a.w) + (r2b.x + r2b.y) + (r2b.z + r2b.w);

        return w * (f - g);
    };

    float vcur = myv;
    sm->wsh[tid] = vcur;
    __syncthreads();

    // ---- Phase 3: 8 RK4 substeps over [t0, t1] ----
    for (int stp = 0; stp < NSUB; ++stp) {
        float k1 = dxdt(vcur);
        float w2s = vcur + 0.5f * dt * k1;
        sm->wsh[tid] = w2s; __syncthreads();
        float k2 = dxdt(w2s);
        float w3s = vcur + 0.5f * dt * k2;
        sm->wsh[tid] = w3s; __syncthreads();
        float k3 = dxdt(w3s);
        float w4s = vcur + dt * k3;
        sm->wsh[tid] = w4s; __syncthreads();
        float k4 = dxdt(w4s);
        vcur += dt * (1.0f / 6.0f) * (k1 + 2.0f * k2 + 2.0f * k3 + k4);
        sm->wsh[tid] = vcur; __syncthreads();
    }

    // t=1 plane
    out[(size_t)BATCH * DATA_DIM + (size_t)b * DATA_DIM + (p - 1)] = vcur;
}

// ---------------------------------------------------------------------------
// kernel_launch
// ---------------------------------------------------------------------------
extern "C" void kernel_launch(void* const* d_in, const int* in_sizes, int n_in,
                              void* d_out, int out_size) {
    const float* t     = (const float*)d_in[0];
    const float* x     = (const float*)d_in[1];
    const float* embed = (const float*)d_in[2];
    const float* Wq    = (const float*)d_in[3];
    const float* bq    = (const float*)d_in[4];
    const float* Wk    = (const float*)d_in[5];
    const float* bk    = (const float*)d_in[6];
    float* out = (float*)d_out;

    cudaFuncSetAttribute(integrate_kernel,
                         cudaFuncAttributeMaxDynamicSharedMemorySize,
                         (int)sizeof(SmemC));

    precompute_kernel<<<(DATA_DIM + 1 + 63) / 64, 256>>>(embed, Wq, bq, Wk, bk);
    integrate_kernel<<<BATCH, 256, sizeof(SmemC)>>>(t, x, Wq, Wk, out);
}

// round 5
// speedup vs baseline: 1.1213x; 1.1213x over previous
#include <cuda_runtime.h>
#include <cuda_bf16.h>
#include <cstddef>

#define BATCH    256
#define DATA_DIM 8192
#define NNZ      256
#define QK       64
#define EMB      63
#define NSUB     8
#define K0S      260   // stride (floats) for transposed k0 staging; conflict-free LDS.128

typedef unsigned long long u64;

// Precomputed per-row projections of the embedding table (row 0 = padding row).
__device__ float4 g_Q0T[(DATA_DIM + 1) * 16];
__device__ float4 g_K0T[(DATA_DIM + 1) * 16];
// W transposed to [e][d] row-major (64x64), for L1-hot float4 reads.
__device__ float4 g_WqT[64 * 16];
__device__ float4 g_WkT[64 * 16];

// packed f32x2 FMA: acc = a*b + acc
__device__ __forceinline__ void fma2(u64& acc, u64 a, u64 b) {
    asm("fma.rn.f32x2 %0, %1, %2, %0;" : "+l"(acc) : "l"(a), "l"(b));
}
__device__ __forceinline__ float hsum2(u64 a) {
    return __uint_as_float((unsigned)a) + __uint_as_float((unsigned)(a >> 32));
}

// ---------------------------------------------------------------------------
// Kernel T: transpose Wq/Wk (64x64) into [e][d] layout. One block.
// ---------------------------------------------------------------------------
__global__ void transpose_kernel(const float* __restrict__ Wq,
                                 const float* __restrict__ Wk) {
    const int tid = threadIdx.x;
    float* wqt = reinterpret_cast<float*>(g_WqT);
    float* wkt = reinterpret_cast<float*>(g_WkT);
    for (int i = tid; i < 4096; i += 256) {
        int d = i >> 6, e = i & 63;
        wqt[e * 64 + d] = Wq[i];
        wkt[e * 64 + d] = Wk[i];
    }
}

// ---------------------------------------------------------------------------
// Kernel P: barrier-free precompute. thread = (p, d4); 63 L1-hot float4 MACs.
// Q0T[p][d] = bq[d] + sum_e embed[p][e] * WqT[e+1][d]
// ---------------------------------------------------------------------------
__global__ void __launch_bounds__(256)
precompute_kernel(const float* __restrict__ embed,
                  const float* __restrict__ bq,
                  const float* __restrict__ bk) {
    const int idx = blockIdx.x * 256 + threadIdx.x;
    const int p = idx >> 4, d4 = idx & 15;
    if (p > DATA_DIM) return;

    float4 aq = __ldg(reinterpret_cast<const float4*>(bq) + d4);
    float4 ak = __ldg(reinterpret_cast<const float4*>(bk) + d4);
    const float* erow = embed + (size_t)p * EMB;
#pragma unroll 7
    for (int e = 0; e < EMB; ++e) {
        float ev = __ldg(erow + e);
        float4 wq = __ldg(&g_WqT[(e + 1) * 16 + d4]);
        float4 wk = __ldg(&g_WkT[(e + 1) * 16 + d4]);
        aq.x += ev * wq.x; aq.y += ev * wq.y; aq.z += ev * wq.z; aq.w += ev * wq.w;
        ak.x += ev * wk.x; ak.y += ev * wk.y; ak.z += ev * wk.z; ak.w += ev * wk.w;
    }
    g_Q0T[(size_t)p * 16 + d4] = aq;
    g_K0T[(size_t)p * 16 + d4] = ak;
}

// ---------------------------------------------------------------------------
// Kernel C: per-batch condense + RK4 + scatter. R2 structure, but the k0
// column chunk is REGISTER-resident (loaded once via transient staging).
// Per eval, shared traffic is only broadcast w and s reads.
// ---------------------------------------------------------------------------
struct SmemC {
    __align__(16) float k0[64 * K0S];   // transient transpose staging only
    __align__(16) float wsh[NNZ];
    __align__(16) float s[QK];
    __align__(16) float mpart[256];
    __align__(16) float red1[8];        // per-warp w^2 partials
    __align__(16) float red2[8];        // per-warp w*f partials
    __align__(16) float c1p[2];         // a.s partials
    __align__(16) float val[NNZ];
    int   idx[NNZ];
    int   wscan[8];
};

extern __shared__ unsigned char smem_raw[];

__global__ void __launch_bounds__(256, 2)
integrate_kernel(const float* __restrict__ t,
                 const float* __restrict__ x,
                 const float* __restrict__ Wq,
                 const float* __restrict__ Wk,
                 float* __restrict__ out) {
    SmemC* sm = reinterpret_cast<SmemC*>(smem_raw);
    const int tid  = threadIdx.x;
    const int b    = blockIdx.x;
    const int lane = tid & 31;
    const int wid  = tid >> 5;

    // ---- Phase 0: zero this block's two output rows ----
    {
        float4 z = make_float4(0.f, 0.f, 0.f, 0.f);
        float4* o4 = reinterpret_cast<float4*>(out);
        for (int i = tid; i < 2048; i += 256) {
            o4[(size_t)b * 2048 + i] = z;
            o4[(size_t)(BATCH + b) * 2048 + i] = z;
        }
    }

    // ---- Phase 1: scan + order-preserving compaction ----
    float xr[32];
    {
        const float4* xrow4 = reinterpret_cast<const float4*>(x + (size_t)b * DATA_DIM) + tid * 8;
#pragma unroll
        for (int j = 0; j < 8; ++j) {
            float4 f = xrow4[j];
            xr[4 * j + 0] = f.x; xr[4 * j + 1] = f.y;
            xr[4 * j + 2] = f.z; xr[4 * j + 3] = f.w;
        }
    }
    if (tid < NNZ) { sm->val[tid] = 0.0f; sm->idx[tid] = 0; }

    int cnt = 0;
#pragma unroll
    for (int j = 0; j < 32; ++j) cnt += (xr[j] != 0.0f) ? 1 : 0;
    int inc = cnt;
#pragma unroll
    for (int o = 1; o < 32; o <<= 1) {
        int u = __shfl_up_sync(0xffffffffu, inc, o);
        if (lane >= o) inc += u;
    }
    if (lane == 31) sm->wscan[wid] = inc;
    __syncthreads();
    int woff = 0;
#pragma unroll
    for (int wdx = 0; wdx < 8; ++wdx) woff += (wdx < wid) ? sm->wscan[wdx] : 0;
    int o = woff + inc - cnt;
#pragma unroll
    for (int j = 0; j < 32; ++j) {
        float v = xr[j];
        if (v != 0.0f && o < NNZ) {
            sm->val[o] = v;
            sm->idx[o] = tid * 32 + j;
            ++o;
        }
    }
    __syncthreads();

    // ---- Phase 2: q0 row -> regs; k0 transpose-stage -> column regs ----
    const int p     = sm->idx[tid] + 1;
    const float myv = sm->val[tid];

    out[(size_t)b * DATA_DIM + (p - 1)] = myv;   // t=0 plane

    u64 q0p[32];   // my row of Q0 (64 floats as 32 packed pairs)
    {
        const ulonglong2* qrow = reinterpret_cast<const ulonglong2*>(g_Q0T + (size_t)p * 16);
#pragma unroll
        for (int i = 0; i < 16; ++i) {
            ulonglong2 v = qrow[i];
            q0p[2 * i] = v.x; q0p[2 * i + 1] = v.y;
        }
        const float4* krow = g_K0T + (size_t)p * 16;
#pragma unroll
        for (int i = 0; i < 16; ++i) {
            float4 f = krow[i];
            int d = 4 * i;
            sm->k0[(d + 0) * K0S + tid] = f.x;
            sm->k0[(d + 1) * K0S + tid] = f.y;
            sm->k0[(d + 2) * K0S + tid] = f.z;
            sm->k0[(d + 3) * K0S + tid] = f.w;
        }
    }

    float avd = 0.0f, bvd = 0.0f;
    if (tid < QK) { avd = Wq[tid * 64]; bvd = Wk[tid * 64]; }

    const float dt = (t[1] - t[0]) * (1.0f / (float)NSUB);
    const int dd = tid & 63, cc = tid >> 6;
    __syncthreads();

    // my k0 column chunk: K0[dd][64*cc .. 64*cc+63] into 32 packed pairs
    u64 k0p[32];
    {
        const ulonglong2* krowsh =
            reinterpret_cast<const ulonglong2*>(sm->k0 + dd * K0S + cc * 64);
#pragma unroll
        for (int j = 0; j < 16; ++j) {
            ulonglong2 v = krowsh[j];
            k0p[2 * j] = v.x; k0p[2 * j + 1] = v.y;
        }
    }

    const ulonglong2* wvp = reinterpret_cast<const ulonglong2*>(sm->wsh + cc * 64);
    const ulonglong2* svp = reinterpret_cast<const ulonglong2*>(sm->s);

    // stage: publish w + per-warp w^2 partial (caller must __syncthreads after)
    auto stage = [&](float w) {
        sm->wsh[tid] = w;
        float w2 = w * w;
#pragma unroll
        for (int o2 = 16; o2 > 0; o2 >>= 1) w2 += __shfl_xor_sync(0xffffffffu, w2, o2);
        if (lane == 0) sm->red1[wid] = w2;
    };

    // dxdt(w) = w*(f - g);  s = S2*b + K0^T w;  f_i = (c1*w_i + q0_i.s)/8;
    // c1 = a.s;  g = sum_j w_j f_j.   precondition: wsh/red1 staged + synced.
    auto dxdt = [&](float w) -> float {
        u64 a0 = 0ull, a1 = 0ull;
#pragma unroll
        for (int j = 0; j < 16; ++j) {
            ulonglong2 wv = wvp[j];
            fma2(a0, k0p[2 * j], wv.x);
            fma2(a1, k0p[2 * j + 1], wv.y);
        }
        sm->mpart[tid] = hsum2(a0) + hsum2(a1);
        __syncthreads();

        if (tid < QK) {
            float4 r1a = *reinterpret_cast<const float4*>(&sm->red1[0]);
            float4 r1b = *reinterpret_cast<const float4*>(&sm->red1[4]);
            float S2 = (r1a.x + r1a.y) + (r1a.z + r1a.w) + (r1b.x + r1b.y) + (r1b.z + r1b.w);
            float m = sm->mpart[tid] + sm->mpart[tid + 64] +
                      sm->mpart[tid + 128] + sm->mpart[tid + 192];
            float sv = S2 * bvd + m;
            sm->s[tid] = sv;
            float cp = avd * sv;
#pragma unroll
            for (int o2 = 16; o2 > 0; o2 >>= 1) cp += __shfl_xor_sync(0xffffffffu, cp, o2);
            if (lane == 0) sm->c1p[wid] = cp;   // wid = 0 or 1
        }
        __syncthreads();

        u64 q0 = 0ull, q1 = 0ull;
#pragma unroll
        for (int j = 0; j < 16; ++j) {
            ulonglong2 sv = svp[j];
            fma2(q0, q0p[2 * j], sv.x);
            fma2(q1, q0p[2 * j + 1], sv.y);
        }
        float qdot = hsum2(q0) + hsum2(q1);
        float c1 = sm->c1p[0] + sm->c1p[1];
        float f  = (c1 * w + qdot) * 0.125f;   // 1/sqrt(64)

        float wf = w * f;
#pragma unroll
        for (int o2 = 16; o2 > 0; o2 >>= 1) wf += __shfl_xor_sync(0xffffffffu, wf, o2);
        if (lane == 0) sm->red2[wid] = wf;
        __syncthreads();
        float4 r2a = *reinterpret_cast<const float4*>(&sm->red2[0]);
        float4 r2b = *reinterpret_cast<const float4*>(&sm->red2[4]);
        float g = (r2a.x + r2a.y) + (r2a.z + r2a.w) + (r2b.x + r2b.y) + (r2b.z + r2b.w);

        return w * (f - g);
    };

    float vcur = myv;
    stage(vcur);
    __syncthreads();

    // ---- Phase 3: 8 RK4 substeps over [t0, t1] ----
    for (int stp = 0; stp < NSUB; ++stp) {
        float k1 = dxdt(vcur);
        float w2s = vcur + 0.5f * dt * k1;
        stage(w2s); __syncthreads();
        float k2 = dxdt(w2s);
        float w3s = vcur + 0.5f * dt * k2;
        stage(w3s); __syncthreads();
        float k3 = dxdt(w3s);
        float w4s = vcur + dt * k3;
        stage(w4s); __syncthreads();
        float k4 = dxdt(w4s);
        vcur += dt * (1.0f / 6.0f) * (k1 + 2.0f * k2 + 2.0f * k3 + k4);
        stage(vcur); __syncthreads();
    }

    // t=1 plane
    out[(size_t)BATCH * DATA_DIM + (size_t)b * DATA_DIM + (p - 1)] = vcur;
}

// ---------------------------------------------------------------------------
// kernel_launch
// ---------------------------------------------------------------------------
extern "C" void kernel_launch(void* const* d_in, const int* in_sizes, int n_in,
                              void* d_out, int out_size) {
    const float* t     = (const float*)d_in[0];
    const float* x     = (const float*)d_in[1];
    const float* embed = (const float*)d_in[2];
    const float* Wq    = (const float*)d_in[3];
    const float* bq    = (const float*)d_in[4];
    const float* Wk    = (const float*)d_in[5];
    const float* bk    = (const float*)d_in[6];
    float* out = (float*)d_out;

    cudaFuncSetAttribute(integrate_kernel,
                         cudaFuncAttributeMaxDynamicSharedMemorySize,
                         (int)sizeof(SmemC));

    transpose_kernel<<<1, 256>>>(Wq, Wk);
    precompute_kernel<<<((DATA_DIM + 1) * 16 + 255) / 256, 256>>>(embed, bq, bk);
    integrate_kernel<<<BATCH, 256, sizeof(SmemC)>>>(t, x, Wq, Wk, out);
}

// round 6
// speedup vs baseline: 1.3835x; 1.2338x over previous
#include <cuda_runtime.h>
#include <cuda_bf16.h>
#include <cstddef>

#define BATCH    256
#define DATA_DIM 8192
#define NNZ      256
#define QK       64
#define EMB      63
#define NSUB     8
#define K0S      260   // stride (floats) for transposed k0 staging; conflict-free LDS.128
#define WTS      68    // stride for W transpose in precompute shared; aligned float4, conflict-free

typedef unsigned long long u64;

// Precomputed per-row projections of the embedding table (row 0 = padding row).
__device__ float4 g_Q0T[(DATA_DIM + 1) * 16];
__device__ float4 g_K0T[(DATA_DIM + 1) * 16];

// packed f32x2 FMA: acc = a*b + acc
__device__ __forceinline__ void fma2(u64& acc, u64 a, u64 b) {
    asm("fma.rn.f32x2 %0, %1, %2, %0;" : "+l"(acc) : "l"(a), "l"(b));
}
__device__ __forceinline__ float hsum2(u64 a) {
    return __uint_as_float((unsigned)a) + __uint_as_float((unsigned)(a >> 32));
}

// ---------------------------------------------------------------------------
// Kernel P: per-block W transpose to shared, then 16 table rows, one sync.
// Q0T[p][d] = bq[d] + sum_e embed[p][e] * Wq[d][e+1]   (same for K)
// thread = (p_local = tid>>4, d4 = tid&15)
// ---------------------------------------------------------------------------
__global__ void __launch_bounds__(256)
precompute_kernel(const float* __restrict__ embed,
                  const float* __restrict__ Wq,
                  const float* __restrict__ bq,
                  const float* __restrict__ Wk,
                  const float* __restrict__ bk) {
    __shared__ __align__(16) float WqT[64 * WTS];  // [e][d], stride 68
    __shared__ __align__(16) float WkT[64 * WTS];
    __shared__ __align__(16) float es[16][64];

    const int tid = threadIdx.x;
    for (int i = tid; i < 4096; i += 256) {
        int d = i >> 6, e = i & 63;      // coalesced LDG, consecutive-d STS: conflict-free
        WqT[e * WTS + d] = Wq[i];
        WkT[e * WTS + d] = Wk[i];
    }
    const int p0 = blockIdx.x * 16;
    for (int i = tid; i < 16 * 63; i += 256) {
        int r = i / 63, e = i - r * 63;
        int p = p0 + r;
        es[r][e] = (p <= DATA_DIM) ? embed[(size_t)p * EMB + e] : 0.0f;
    }
    __syncthreads();

    const int r = tid >> 4, d4 = tid & 15;
    const int p = p0 + r;
    if (p <= DATA_DIM) {
        float4 aq = __ldg(reinterpret_cast<const float4*>(bq) + d4);
        float4 ak = __ldg(reinterpret_cast<const float4*>(bk) + d4);
#pragma unroll 9
        for (int e = 0; e < EMB; ++e) {
            float ev = es[r][e];
            float4 wq = *reinterpret_cast<const float4*>(&WqT[(e + 1) * WTS + 4 * d4]);
            float4 wk = *reinterpret_cast<const float4*>(&WkT[(e + 1) * WTS + 4 * d4]);
            aq.x += ev * wq.x; aq.y += ev * wq.y; aq.z += ev * wq.z; aq.w += ev * wq.w;
            ak.x += ev * wk.x; ak.y += ev * wk.y; ak.z += ev * wk.z; ak.w += ev * wk.w;
        }
        g_Q0T[(size_t)p * 16 + d4] = aq;
        g_K0T[(size_t)p * 16 + d4] = ak;
    }
}

// ---------------------------------------------------------------------------
// Kernel C: per-batch condense + RK4 + scatter. k0 columns + q0 row TRULY
// register-resident (1 block/SM -> up to 255 regs, no spills). Per eval,
// shared traffic is only broadcast w and s reads.
// ---------------------------------------------------------------------------
struct SmemC {
    __align__(16) float k0[64 * K0S];   // transient transpose staging only
    __align__(16) float wsh[NNZ];
    __align__(16) float s[QK];
    __align__(16) float mpart[256];
    __align__(16) float red1[8];        // per-warp w^2 partials
    __align__(16) float red2[8];        // per-warp w*f partials
    __align__(16) float c1p[2];         // a.s partials
    __align__(16) float val[NNZ];
    int   idx[NNZ];
    int   wscan[8];
};

extern __shared__ unsigned char smem_raw[];

__global__ void __launch_bounds__(256, 1)
integrate_kernel(const float* __restrict__ t,
                 const float* __restrict__ x,
                 const float* __restrict__ Wq,
                 const float* __restrict__ Wk,
                 float* __restrict__ out) {
    SmemC* sm = reinterpret_cast<SmemC*>(smem_raw);
    const int tid  = threadIdx.x;
    const int b    = blockIdx.x;
    const int lane = tid & 31;
    const int wid  = tid >> 5;

    // ---- Phase 0: zero this block's two output rows ----
    {
        float4 z = make_float4(0.f, 0.f, 0.f, 0.f);
        float4* o4 = reinterpret_cast<float4*>(out);
        for (int i = tid; i < 2048; i += 256) {
            o4[(size_t)b * 2048 + i] = z;
            o4[(size_t)(BATCH + b) * 2048 + i] = z;
        }
    }

    // ---- Phase 1: scan + order-preserving compaction ----
    float xr[32];
    {
        const float4* xrow4 = reinterpret_cast<const float4*>(x + (size_t)b * DATA_DIM) + tid * 8;
#pragma unroll
        for (int j = 0; j < 8; ++j) {
            float4 f = xrow4[j];
            xr[4 * j + 0] = f.x; xr[4 * j + 1] = f.y;
            xr[4 * j + 2] = f.z; xr[4 * j + 3] = f.w;
        }
    }
    if (tid < NNZ) { sm->val[tid] = 0.0f; sm->idx[tid] = 0; }

    int cnt = 0;
#pragma unroll
    for (int j = 0; j < 32; ++j) cnt += (xr[j] != 0.0f) ? 1 : 0;
    int inc = cnt;
#pragma unroll
    for (int o = 1; o < 32; o <<= 1) {
        int u = __shfl_up_sync(0xffffffffu, inc, o);
        if (lane >= o) inc += u;
    }
    if (lane == 31) sm->wscan[wid] = inc;
    __syncthreads();
    int woff = 0;
#pragma unroll
    for (int wdx = 0; wdx < 8; ++wdx) woff += (wdx < wid) ? sm->wscan[wdx] : 0;
    int o = woff + inc - cnt;
#pragma unroll
    for (int j = 0; j < 32; ++j) {
        float v = xr[j];
        if (v != 0.0f && o < NNZ) {
            sm->val[o] = v;
            sm->idx[o] = tid * 32 + j;
            ++o;
        }
    }
    __syncthreads();

    // ---- Phase 2: q0 row -> regs; k0 transpose-stage -> column regs ----
    const int p     = sm->idx[tid] + 1;
    const float myv = sm->val[tid];

    out[(size_t)b * DATA_DIM + (p - 1)] = myv;   // t=0 plane

    u64 q0p[32];   // my row of Q0 (64 floats as 32 packed pairs)
    {
        const ulonglong2* qrow = reinterpret_cast<const ulonglong2*>(g_Q0T + (size_t)p * 16);
#pragma unroll
        for (int i = 0; i < 16; ++i) {
            ulonglong2 v = qrow[i];
            q0p[2 * i] = v.x; q0p[2 * i + 1] = v.y;
        }
        const float4* krow = g_K0T + (size_t)p * 16;
#pragma unroll
        for (int i = 0; i < 16; ++i) {
            float4 f = krow[i];
            int d = 4 * i;
            sm->k0[(d + 0) * K0S + tid] = f.x;
            sm->k0[(d + 1) * K0S + tid] = f.y;
            sm->k0[(d + 2) * K0S + tid] = f.z;
            sm->k0[(d + 3) * K0S + tid] = f.w;
        }
    }

    float avd = 0.0f, bvd = 0.0f;
    if (tid < QK) { avd = Wq[tid * 64]; bvd = Wk[tid * 64]; }

    const float dt = (t[1] - t[0]) * (1.0f / (float)NSUB);
    const int dd = tid & 63, cc = tid >> 6;
    __syncthreads();

    // my k0 column chunk: K0[dd][64*cc .. 64*cc+63] into 32 packed pairs
    u64 k0p[32];
    {
        const ulonglong2* krowsh =
            reinterpret_cast<const ulonglong2*>(sm->k0 + dd * K0S + cc * 64);
#pragma unroll
        for (int j = 0; j < 16; ++j) {
            ulonglong2 v = krowsh[j];
            k0p[2 * j] = v.x; k0p[2 * j + 1] = v.y;
        }
    }

    const ulonglong2* wvp = reinterpret_cast<const ulonglong2*>(sm->wsh + cc * 64);
    const ulonglong2* svp = reinterpret_cast<const ulonglong2*>(sm->s);

    // dxdt(w) = w*(f - g);  s = S2*b + K0^T w;  f_i = (c1*w_i + q0_i.s)/8;
    // c1 = a.s;  g = sum_j w_j f_j.
    // precondition: sm->wsh holds w (staged + synced). The w^2 tree runs
    // AFTER the m-loop issue so its shfl latency overlaps the FMA chain.
    auto dxdt = [&](float w) -> float {
        u64 a0 = 0ull, a1 = 0ull;
#pragma unroll
        for (int j = 0; j < 16; ++j) {
            ulonglong2 wv = wvp[j];
            fma2(a0, k0p[2 * j], wv.x);
            fma2(a1, k0p[2 * j + 1], wv.y);
        }
        sm->mpart[tid] = hsum2(a0) + hsum2(a1);

        float w2 = w * w;
#pragma unroll
        for (int o2 = 16; o2 > 0; o2 >>= 1) w2 += __shfl_xor_sync(0xffffffffu, w2, o2);
        if (lane == 0) sm->red1[wid] = w2;
        __syncthreads();

        if (tid < QK) {
            float4 r1a = *reinterpret_cast<const float4*>(&sm->red1[0]);
            float4 r1b = *reinterpret_cast<const float4*>(&sm->red1[4]);
            float S2 = (r1a.x + r1a.y) + (r1a.z + r1a.w) + (r1b.x + r1b.y) + (r1b.z + r1b.w);
            float m = sm->mpart[tid] + sm->mpart[tid + 64] +
                      sm->mpart[tid + 128] + sm->mpart[tid + 192];
            float sv = S2 * bvd + m;
            sm->s[tid] = sv;
            float cp = avd * sv;
#pragma unroll
            for (int o2 = 16; o2 > 0; o2 >>= 1) cp += __shfl_xor_sync(0xffffffffu, cp, o2);
            if (lane == 0) sm->c1p[wid] = cp;   // wid = 0 or 1
        }
        __syncthreads();

        u64 q0 = 0ull, q1 = 0ull;
#pragma unroll
        for (int j = 0; j < 16; ++j) {
            ulonglong2 sv = svp[j];
            fma2(q0, q0p[2 * j], sv.x);
            fma2(q1, q0p[2 * j + 1], sv.y);
        }
        float qdot = hsum2(q0) + hsum2(q1);
        float c1 = sm->c1p[0] + sm->c1p[1];
        float f  = (c1 * w + qdot) * 0.125f;   // 1/sqrt(64)

        float wf = w * f;
#pragma unroll
        for (int o2 = 16; o2 > 0; o2 >>= 1) wf += __shfl_xor_sync(0xffffffffu, wf, o2);
        if (lane == 0) sm->red2[wid] = wf;
        __syncthreads();
        float4 r2a = *reinterpret_cast<const float4*>(&sm->red2[0]);
        float4 r2b = *reinterpret_cast<const float4*>(&sm->red2[4]);
        float g = (r2a.x + r2a.y) + (r2a.z + r2a.w) + (r2b.x + r2b.y) + (r2b.z + r2b.w);

        return w * (f - g);
    };

    float vcur = myv;
    sm->wsh[tid] = vcur;
    __syncthreads();

    // ---- Phase 3: 8 RK4 substeps over [t0, t1] ----
    for (int stp = 0; stp < NSUB; ++stp) {
        float k1 = dxdt(vcur);
        float w2s = vcur + 0.5f * dt * k1;
        sm->wsh[tid] = w2s; __syncthreads();
        float k2 = dxdt(w2s);
        float w3s = vcur + 0.5f * dt * k2;
        sm->wsh[tid] = w3s; __syncthreads();
        float k3 = dxdt(w3s);
        float w4s = vcur + dt * k3;
        sm->wsh[tid] = w4s; __syncthreads();
        float k4 = dxdt(w4s);
        vcur += dt * (1.0f / 6.0f) * (k1 + 2.0f * k2 + 2.0f * k3 + k4);
        sm->wsh[tid] = vcur; __syncthreads();
    }

    // t=1 plane
    out[(size_t)BATCH * DATA_DIM + (size_t)b * DATA_DIM + (p - 1)] = vcur;
}

// ---------------------------------------------------------------------------
// kernel_launch
// ---------------------------------------------------------------------------
extern "C" void kernel_launch(void* const* d_in, const int* in_sizes, int n_in,
                              void* d_out, int out_size) {
    const float* t     = (const float*)d_in[0];
    const float* x     = (const float*)d_in[1];
    const float* embed = (const float*)d_in[2];
    const float* Wq    = (const float*)d_in[3];
    const float* bq    = (const float*)d_in[4];
    const float* Wk    = (const float*)d_in[5];
    const float* bk    = (const float*)d_in[6];
    float* out = (float*)d_out;

    cudaFuncSetAttribute(integrate_kernel,
                         cudaFuncAttributeMaxDynamicSharedMemorySize,
                         (int)sizeof(SmemC));

    precompute_kernel<<<(DATA_DIM + 1 + 15) / 16, 256>>>(embed, Wq, bq, Wk, bk);
    integrate_kernel<<<BATCH, 256, sizeof(SmemC)>>>(t, x, Wq, Wk, out);
}

// round 7
// speedup vs baseline: 1.3841x; 1.0004x over previous
#include <cuda_runtime.h>
#include <cstddef>

#define BATCH    256
#define DATA_DIM 8192
#define NNZ      256
#define QK       64
#define EMB      63
#define NSUB     8
#define WTS      68    // stride for W transpose in precompute shared
#define Q0S      68    // stride (floats) for q0 rows in shared; 17 float4 -> conflict-free LDS.128

typedef unsigned long long u64;

// Precomputed per-row projections of the embedding table (row 0 = padding row).
__device__ float4 g_Q0T[(DATA_DIM + 1) * 16];
__device__ float4 g_K0T[(DATA_DIM + 1) * 16];

// packed f32x2 FMA: acc = a*b + acc
__device__ __forceinline__ void fma2(u64& acc, u64 a, u64 b) {
    asm("fma.rn.f32x2 %0, %1, %2, %0;" : "+l"(acc) : "l"(a), "l"(b));
}
__device__ __forceinline__ float hsum2(u64 a) {
    return __uint_as_float((unsigned)a) + __uint_as_float((unsigned)(a >> 32));
}
__device__ __forceinline__ u64 pack2(float lo, float hi) {
    u64 r;
    asm("mov.b64 %0, {%1, %2};" : "=l"(r) : "f"(lo), "f"(hi));
    return r;
}

// ---------------------------------------------------------------------------
// Kernel P: per-block W transpose to shared, then 16 table rows, one sync.
// Q0T[p][d] = bq[d] + sum_e embed[p][e] * Wq[d][e+1]   (same for K)
// ---------------------------------------------------------------------------
__global__ void __launch_bounds__(256)
precompute_kernel(const float* __restrict__ embed,
                  const float* __restrict__ Wq,
                  const float* __restrict__ bq,
                  const float* __restrict__ Wk,
                  const float* __restrict__ bk) {
    __shared__ __align__(16) float WqT[64 * WTS];
    __shared__ __align__(16) float WkT[64 * WTS];
    __shared__ __align__(16) float es[16][64];

    const int tid = threadIdx.x;
    for (int i = tid; i < 4096; i += 256) {
        int d = i >> 6, e = i & 63;
        WqT[e * WTS + d] = Wq[i];
        WkT[e * WTS + d] = Wk[i];
    }
    const int p0 = blockIdx.x * 16;
    for (int i = tid; i < 16 * 63; i += 256) {
        int r = i / 63, e = i - r * 63;
        int p = p0 + r;
        es[r][e] = (p <= DATA_DIM) ? embed[(size_t)p * EMB + e] : 0.0f;
    }
    __syncthreads();

    const int r = tid >> 4, d4 = tid & 15;
    const int p = p0 + r;
    if (p <= DATA_DIM) {
        float4 aq = __ldg(reinterpret_cast<const float4*>(bq) + d4);
        float4 ak = __ldg(reinterpret_cast<const float4*>(bk) + d4);
#pragma unroll 9
        for (int e = 0; e < EMB; ++e) {
            float ev = es[r][e];
            float4 wq = *reinterpret_cast<const float4*>(&WqT[(e + 1) * WTS + 4 * d4]);
            float4 wk = *reinterpret_cast<const float4*>(&WkT[(e + 1) * WTS + 4 * d4]);
            aq.x += ev * wq.x; aq.y += ev * wq.y; aq.z += ev * wq.z; aq.w += ev * wq.w;
            ak.x += ev * wk.x; ak.y += ev * wk.y; ak.z += ev * wk.z; ak.w += ev * wk.w;
        }
        g_Q0T[(size_t)p * 16 + d4] = aq;
        g_K0T[(size_t)p * 16 + d4] = ak;
    }
}

// ---------------------------------------------------------------------------
// Kernel C: per-batch condense + RK4 + scatter.
// k0 column chunk in registers (direct coalesced LDG gather, no staging);
// q0 rows in shared (own-row reads, conflict-free). 2 blocks/SM -> 1 wave.
// ---------------------------------------------------------------------------
struct SmemC {
    __align__(16) float q0sh[NNZ * Q0S];   // 69.6 KB, permanent
    __align__(16) float wsh[NNZ];
    __align__(16) float s[QK];
    __align__(16) float mpart[256];
    __align__(16) float red1[8];           // per-warp w^2 partials
    __align__(16) float red2[8];           // per-warp w*f partials
    __align__(16) float c1p[2];            // a.s partials
    __align__(16) float val[NNZ];
    int   idx[NNZ];
    int   wscan[8];
};

extern __shared__ unsigned char smem_raw[];

__global__ void __launch_bounds__(256, 2)
integrate_kernel(const float* __restrict__ t,
                 const float* __restrict__ x,
                 const float* __restrict__ Wq,
                 const float* __restrict__ Wk,
                 float* __restrict__ out) {
    SmemC* sm = reinterpret_cast<SmemC*>(smem_raw);
    const int tid  = threadIdx.x;
    const int b    = blockIdx.x;
    const int lane = tid & 31;
    const int wid  = tid >> 5;

    // ---- Phase 0: zero this block's two output rows ----
    {
        float4 z = make_float4(0.f, 0.f, 0.f, 0.f);
        float4* o4 = reinterpret_cast<float4*>(out);
        for (int i = tid; i < 2048; i += 256) {
            o4[(size_t)b * 2048 + i] = z;
            o4[(size_t)(BATCH + b) * 2048 + i] = z;
        }
    }

    // ---- Phase 1: scan + order-preserving compaction ----
    float xr[32];
    {
        const float4* xrow4 = reinterpret_cast<const float4*>(x + (size_t)b * DATA_DIM) + tid * 8;
#pragma unroll
        for (int j = 0; j < 8; ++j) {
            float4 f = xrow4[j];
            xr[4 * j + 0] = f.x; xr[4 * j + 1] = f.y;
            xr[4 * j + 2] = f.z; xr[4 * j + 3] = f.w;
        }
    }
    if (tid < NNZ) { sm->val[tid] = 0.0f; sm->idx[tid] = 0; }

    int cnt = 0;
#pragma unroll
    for (int j = 0; j < 32; ++j) cnt += (xr[j] != 0.0f) ? 1 : 0;
    int inc = cnt;
#pragma unroll
    for (int o = 1; o < 32; o <<= 1) {
        int u = __shfl_up_sync(0xffffffffu, inc, o);
        if (lane >= o) inc += u;
    }
    if (lane == 31) sm->wscan[wid] = inc;
    __syncthreads();
    int woff = 0;
#pragma unroll
    for (int wdx = 0; wdx < 8; ++wdx) woff += (wdx < wid) ? sm->wscan[wdx] : 0;
    int o = woff + inc - cnt;
#pragma unroll
    for (int j = 0; j < 32; ++j) {
        float v = xr[j];
        if (v != 0.0f && o < NNZ) {
            sm->val[o] = v;
            sm->idx[o] = tid * 32 + j;
            ++o;
        }
    }
    __syncthreads();

    // ---- Phase 2: q0 row -> shared (own row); k0 column -> registers ----
    const int p     = sm->idx[tid] + 1;
    const float myv = sm->val[tid];

    out[(size_t)b * DATA_DIM + (p - 1)] = myv;   // t=0 plane

    // my q0 row into shared (read back only by this thread)
    {
        const float4* qrow = g_Q0T + (size_t)p * 16;
        float4* dst = reinterpret_cast<float4*>(&sm->q0sh[tid * Q0S]);
#pragma unroll
        for (int i = 0; i < 16; ++i) dst[i] = qrow[i];
    }

    const int dd = tid & 63, cc = tid >> 6;

    // k0 column chunk K0[dd][cc*64 .. cc*64+63] via coalesced LDG gather
    // (warp lanes have consecutive dd -> each LDG is a 128B segment)
    u64 k0u[32];
    {
        const float* k0g = reinterpret_cast<const float*>(g_K0T);
        const int ib = cc * 64;
#pragma unroll
        for (int j = 0; j < 32; ++j) {
            int pa = sm->idx[ib + 2 * j] + 1;
            int pb = sm->idx[ib + 2 * j + 1] + 1;
            float fa = __ldg(k0g + (size_t)pa * 64 + dd);
            float fb = __ldg(k0g + (size_t)pb * 64 + dd);
            k0u[j] = pack2(fa, fb);
        }
    }

    float avd = 0.0f, bvd = 0.0f;
    if (tid < QK) { avd = Wq[tid * 64]; bvd = Wk[tid * 64]; }

    const float dt = (t[1] - t[0]) * (1.0f / (float)NSUB);
    const ulonglong2* wvp    = reinterpret_cast<const ulonglong2*>(sm->wsh + cc * 64);
    const ulonglong2* svp    = reinterpret_cast<const ulonglong2*>(sm->s);
    const ulonglong2* q0row2 = reinterpret_cast<const ulonglong2*>(&sm->q0sh[tid * Q0S]);

    // dxdt(w) = w*(f - g);  s = S2*b + K0^T w;  f_i = (c1*w_i + q0_i.s)/8;
    // c1 = a.s;  g = sum_j w_j f_j.  precondition: wsh staged + synced.
    auto dxdt = [&](float w) -> float {
        u64 a0 = 0ull, a1 = 0ull;
#pragma unroll
        for (int j = 0; j < 16; ++j) {
            ulonglong2 wv = wvp[j];
            fma2(a0, k0u[2 * j], wv.x);
            fma2(a1, k0u[2 * j + 1], wv.y);
        }
        sm->mpart[tid] = hsum2(a0) + hsum2(a1);

        float w2 = w * w;
#pragma unroll
        for (int o2 = 16; o2 > 0; o2 >>= 1) w2 += __shfl_xor_sync(0xffffffffu, w2, o2);
        if (lane == 0) sm->red1[wid] = w2;
        __syncthreads();                                   // BAR A

        if (tid < QK) {
            float4 r1a = *reinterpret_cast<const float4*>(&sm->red1[0]);
            float4 r1b = *reinterpret_cast<const float4*>(&sm->red1[4]);
            float S2 = (r1a.x + r1a.y) + (r1a.z + r1a.w) + (r1b.x + r1b.y) + (r1b.z + r1b.w);
            float m = sm->mpart[tid] + sm->mpart[tid + 64] +
                      sm->mpart[tid + 128] + sm->mpart[tid + 192];
            float sv = S2 * bvd + m;
            sm->s[tid] = sv;
            float cp = avd * sv;
#pragma unroll
            for (int o2 = 16; o2 > 0; o2 >>= 1) cp += __shfl_xor_sync(0xffffffffu, cp, o2);
            if (lane == 0) sm->c1p[wid] = cp;              // wid = 0 or 1
        }
        __syncthreads();                                   // BAR B

        u64 q0 = 0ull, q1 = 0ull;
#pragma unroll
        for (int j = 0; j < 16; ++j) {
            ulonglong2 qv = q0row2[j];
            ulonglong2 sv = svp[j];
            fma2(q0, qv.x, sv.x);
            fma2(q1, qv.y, sv.y);
        }
        float qdot = hsum2(q0) + hsum2(q1);
        float c1 = sm->c1p[0] + sm->c1p[1];
        float f  = (c1 * w + qdot) * 0.125f;               // 1/sqrt(64)

        float wf = w * f;
#pragma unroll
        for (int o2 = 16; o2 > 0; o2 >>= 1) wf += __shfl_xor_sync(0xffffffffu, wf, o2);
        if (lane == 0) sm->red2[wid] = wf;
        __syncthreads();                                   // BAR C
        float4 r2a = *reinterpret_cast<const float4*>(&sm->red2[0]);
        float4 r2b = *reinterpret_cast<const float4*>(&sm->red2[4]);
        float g = (r2a.x + r2a.y) + (r2a.z + r2a.w) + (r2b.x + r2b.y) + (r2b.z + r2b.w);

        return w * (f - g);
    };

    float vcur = myv;
    sm->wsh[tid] = vcur;
    __syncthreads();

    // ---- Phase 3: 8 RK4 substeps over [t0, t1] ----
    for (int stp = 0; stp < NSUB; ++stp) {
        float k1 = dxdt(vcur);
        float w2s = vcur + 0.5f * dt * k1;
        sm->wsh[tid] = w2s; __syncthreads();
        float k2 = dxdt(w2s);
        float w3s = vcur + 0.5f * dt * k2;
        sm->wsh[tid] = w3s; __syncthreads();
        float k3 = dxdt(w3s);
        float w4s = vcur + dt * k3;
        sm->wsh[tid] = w4s; __syncthreads();
        float k4 = dxdt(w4s);
        vcur += dt * (1.0f / 6.0f) * (k1 + 2.0f * k2 + 2.0f * k3 + k4);
        sm->wsh[tid] = vcur; __syncthreads();
    }

    // t=1 plane
    out[(size_t)BATCH * DATA_DIM + (size_t)b * DATA_DIM + (p - 1)] = vcur;
}

// ---------------------------------------------------------------------------
// kernel_launch
// ---------------------------------------------------------------------------
extern "C" void kernel_launch(void* const* d_in, const int* in_sizes, int n_in,
                              void* d_out, int out_size) {
    const float* t     = (const float*)d_in[0];
    const float* x     = (const float*)d_in[1];
    const float* embed = (const float*)d_in[2];
    const float* Wq    = (const float*)d_in[3];
    const float* bq    = (const float*)d_in[4];
    const float* Wk    = (const float*)d_in[5];
    const float* bk    = (const float*)d_in[6];
    float* out = (float*)d_out;

    cudaFuncSetAttribute(integrate_kernel,
                         cudaFuncAttributeMaxDynamicSharedMemorySize,
                         (int)sizeof(SmemC));

    precompute_kernel<<<(DATA_DIM + 1 + 15) / 16, 256>>>(embed, Wq, bq, Wk, bk);
    integrate_kernel<<<BATCH, 256, sizeof(SmemC)>>>(t, x, Wq, Wk, out);
}